// round 11
// baseline (speedup 1.0000x reference)
#include <cuda_runtime.h>
#include <cuda_bf16.h>
#include <cstdint>

#define DIM 1024
#define NH 16
#define HD 64
#define BT 4096            // B*T tokens
#define TSEQ 2048
#define GROUP 128

// ---------------- scratch (device globals; no allocation allowed) ----------------
__device__ int8_t g_wi[4 * DIM * DIM];   // ternary weights as int8: q,k,v,o
__device__ float  g_ws[4 * DIM * 8];     // per-(matrix,row,group) scales
__device__ int8_t g_xi[BT * DIM];        // int8 activations (reused)
__device__ float  g_sx[BT];              // per-token 1/s (dequant scale)
__device__ float  g_q [BT * DIM];
__device__ float  g_k [BT * DIM];
__device__ float  g_v [BT * DIM];
__device__ float  g_ao[BT * DIM];        // attention output
// pre-converted split-bf16 K (rope applied) and V (transposed)
__device__ uint32_t g_khi[2 * NH * TSEQ * 32];   // [bh][key][dpair]
__device__ uint32_t g_klo[2 * NH * TSEQ * 32];
__device__ uint32_t g_vhi[2 * NH * HD * (TSEQ / 2)]; // [bh][d][keypair]
__device__ uint32_t g_vlo[2 * NH * HD * (TSEQ / 2)];

// ---------------- weight quantization: per-(row,group) ternary -> int8 -----------
__global__ void quant_w_kernel(const float* __restrict__ w0, const float* __restrict__ w1,
                               const float* __restrict__ w2, const float* __restrict__ w3) {
    int blk = blockIdx.x;
    int g   = blk & 7;
    int row = (blk >> 3) & (DIM - 1);
    int m   = blk >> 13;
    const float* w = (m == 0) ? w0 : (m == 1) ? w1 : (m == 2) ? w2 : w3;
    int base = row * DIM + g * GROUP;
    float v = w[base + threadIdx.x];
    float a = fabsf(v);
    #pragma unroll
    for (int o = 16; o; o >>= 1) a += __shfl_xor_sync(0xffffffffu, a, o);
    __shared__ float sh[4];
    if ((threadIdx.x & 31) == 0) sh[threadIdx.x >> 5] = a;
    __syncthreads();
    float ws = (sh[0] + sh[1] + sh[2] + sh[3]) * (1.0f / GROUP) + 1e-5f;
    float q = fminf(fmaxf(rintf(v / ws), -1.f), 1.f);
    g_wi[m * (DIM * DIM) + base + threadIdx.x] = (int8_t)q;
    if (threadIdx.x == 0) g_ws[(m * DIM + row) * 8 + g] = ws;
}

// ---------------- activation quantization: per-token absmax -> int8 --------------
__global__ void quant_x_kernel(const float* __restrict__ x, int8_t* __restrict__ xi,
                               float* __restrict__ sx) {
    int tkn = blockIdx.x;
    const float* xr = x + (size_t)tkn * DIM;
    float mx = 0.f;
    for (int i = threadIdx.x; i < DIM; i += 256) mx = fmaxf(mx, fabsf(xr[i]));
    #pragma unroll
    for (int o = 16; o; o >>= 1) mx = fmaxf(mx, __shfl_xor_sync(0xffffffffu, mx, o));
    __shared__ float sh[8];
    if ((threadIdx.x & 31) == 0) sh[threadIdx.x >> 5] = mx;
    __syncthreads();
    float m = sh[0];
    #pragma unroll
    for (int i = 1; i < 8; i++) m = fmaxf(m, sh[i]);
    float s = 127.f / (m + 1e-5f);
    for (int i = threadIdx.x; i < DIM; i += 256) {
        float v = xr[i];
        xi[(size_t)tkn * DIM + i] = (int8_t)fminf(fmaxf(rintf(v * s), -128.f), 127.f);
    }
    if (threadIdx.x == 0) sx[tkn] = 1.0f / s;
}

// ---------------- int8 tensor-core GEMM: ldmatrix + cp.async double buffer --------
__device__ __forceinline__ void mma_s8(int* d, const int* a, const int* b) {
    asm volatile("mma.sync.aligned.m16n8k32.row.col.s32.s8.s8.s32 "
        "{%0,%1,%2,%3}, {%4,%5,%6,%7}, {%8,%9}, {%0,%1,%2,%3};\n"
        : "+r"(d[0]), "+r"(d[1]), "+r"(d[2]), "+r"(d[3])
        : "r"(a[0]), "r"(a[1]), "r"(a[2]), "r"(a[3]), "r"(b[0]), "r"(b[1]));
}
__device__ __forceinline__ void ldsm4(int& r0, int& r1, int& r2, int& r3, uint32_t addr) {
    asm volatile("ldmatrix.sync.aligned.m8n8.x4.shared.b16 {%0,%1,%2,%3}, [%4];"
        : "=r"(r0), "=r"(r1), "=r"(r2), "=r"(r3) : "r"(addr));
}
__device__ __forceinline__ void cp_async16(uint32_t s, const void* g) {
    asm volatile("cp.async.cg.shared.global [%0], [%1], 16;" :: "r"(s), "l"(g) : "memory");
}

#define GPAD 144
#define GBUF (128 * GPAD)
#define SMEM_GEMM (4 * GBUF + 8 * 128 * 4)

__global__ __launch_bounds__(256, 1)
void gemm_i8mma_kernel(const int8_t* __restrict__ Xi, const int8_t* __restrict__ WiB,
                       const float* __restrict__ wsB, const float* __restrict__ sx,
                       float* __restrict__ C0, float* __restrict__ C1, float* __restrict__ C2) {
    extern __shared__ int8_t smem[];
    int8_t* As = smem;
    int8_t* Bs = smem + 2 * GBUF;
    float*  wss = (float*)(smem + 4 * GBUF);
    uint32_t sA = (uint32_t)__cvta_generic_to_shared(As);
    uint32_t sB = (uint32_t)__cvta_generic_to_shared(Bs);

    int z = blockIdx.z;
    const int8_t* Wi = WiB + (size_t)z * DIM * DIM;
    const float*  ws = wsB + z * DIM * 8;
    float* C = (z == 0) ? C0 : (z == 1) ? C1 : C2;

    int t = threadIdx.x;
    int rowBlk = blockIdx.y * 128;
    int colBlk = blockIdx.x * 128;
    int warpId = t >> 5, lane = t & 31;
    int gid = lane >> 2, tig = lane & 3;
    int wm = (warpId >> 2) * 64;
    int wn = (warpId & 3) * 32;

    for (int i = t; i < 8 * 128; i += 256) {
        int col = i & 127, g = i >> 7;
        wss[g * 128 + col] = ws[(colBlk + col) * 8 + g];
    }

    int sel = lane >> 3;
    uint32_t aOff = (uint32_t)((wm + (sel & 1) * 8 + (lane & 7)) * GPAD + (sel >> 1) * 16);
    uint32_t bOff = (uint32_t)((wn + (sel >> 1) * 8 + (lane & 7)) * GPAD + (sel & 1) * 16);

    int   iacc[4][4][4];
    float facc[4][4][4];
    #pragma unroll
    for (int mt = 0; mt < 4; mt++)
        #pragma unroll
        for (int nt = 0; nt < 4; nt++)
            #pragma unroll
            for (int r = 0; r < 4; r++) { iacc[mt][nt][r] = 0; facc[mt][nt][r] = 0.f; }

    {
        #pragma unroll
        for (int r = 0; r < 4; r++) {
            int u = t + 256 * r;
            int row = u >> 3, c = u & 7;
            cp_async16(sA + row * GPAD + c * 16,
                       Xi + (size_t)(rowBlk + row) * DIM + c * 16);
            cp_async16(sB + row * GPAD + c * 16,
                       Wi + (size_t)(colBlk + row) * DIM + c * 16);
        }
        asm volatile("cp.async.commit_group;" ::: "memory");
    }

    for (int g = 0; g < 8; g++) {
        asm volatile("cp.async.wait_group 0;" ::: "memory");
        __syncthreads();
        if (g < 7) {
            int k0 = (g + 1) * GROUP;
            uint32_t dst = ((g + 1) & 1) * GBUF;
            #pragma unroll
            for (int r = 0; r < 4; r++) {
                int u = t + 256 * r;
                int row = u >> 3, c = u & 7;
                cp_async16(sA + dst + row * GPAD + c * 16,
                           Xi + (size_t)(rowBlk + row) * DIM + k0 + c * 16);
                cp_async16(sB + dst + row * GPAD + c * 16,
                           Wi + (size_t)(colBlk + row) * DIM + k0 + c * 16);
            }
            asm volatile("cp.async.commit_group;" ::: "memory");
        }

        uint32_t bufA = sA + (g & 1) * GBUF + aOff;
        uint32_t bufB = sB + (g & 1) * GBUF + bOff;
        #pragma unroll
        for (int ks = 0; ks < 4; ks++) {
            int a[4][4], b[4][2];
            #pragma unroll
            for (int mt = 0; mt < 4; mt++)
                ldsm4(a[mt][0], a[mt][1], a[mt][2], a[mt][3],
                      bufA + mt * 16 * GPAD + ks * 32);
            #pragma unroll
            for (int ntp = 0; ntp < 2; ntp++)
                ldsm4(b[2 * ntp][0], b[2 * ntp][1], b[2 * ntp + 1][0], b[2 * ntp + 1][1],
                      bufB + ntp * 16 * GPAD + ks * 32);
            #pragma unroll
            for (int mt = 0; mt < 4; mt++)
                #pragma unroll
                for (int nt = 0; nt < 4; nt++)
                    mma_s8(iacc[mt][nt], a[mt], b[nt]);
        }

        #pragma unroll
        for (int nt = 0; nt < 4; nt++) {
            float w0 = wss[g * 128 + wn + nt * 8 + 2 * tig];
            float w1 = wss[g * 128 + wn + nt * 8 + 2 * tig + 1];
            #pragma unroll
            for (int mt = 0; mt < 4; mt++) {
                facc[mt][nt][0] += w0 * (float)iacc[mt][nt][0]; iacc[mt][nt][0] = 0;
                facc[mt][nt][1] += w1 * (float)iacc[mt][nt][1]; iacc[mt][nt][1] = 0;
                facc[mt][nt][2] += w0 * (float)iacc[mt][nt][2]; iacc[mt][nt][2] = 0;
                facc[mt][nt][3] += w1 * (float)iacc[mt][nt][3]; iacc[mt][nt][3] = 0;
            }
        }
    }

    #pragma unroll
    for (int mt = 0; mt < 4; mt++) {
        int row0 = rowBlk + wm + mt * 16 + gid;
        float s0 = sx[row0], s1 = sx[row0 + 8];
        #pragma unroll
        for (int nt = 0; nt < 4; nt++) {
            int col = colBlk + wn + nt * 8 + 2 * tig;
            *(float2*)&C[(size_t)row0 * DIM + col] =
                make_float2(facc[mt][nt][0] * s0, facc[mt][nt][1] * s0);
            *(float2*)&C[(size_t)(row0 + 8) * DIM + col] =
                make_float2(facc[mt][nt][2] * s1, facc[mt][nt][3] * s1);
        }
    }
}

// ---------------- helpers: split bf16 ---------------------------------------------
__device__ __forceinline__ uint32_t pack_bf16x2(float e, float o) {
    uint32_t r; asm("cvt.rn.bf16x2.f32 %0, %1, %2;" : "=r"(r) : "f"(o), "f"(e)); return r;
}
__device__ __forceinline__ void split_bf16x2(float e, float o, uint32_t& hi, uint32_t& lo) {
    hi = pack_bf16x2(e, o);
    float eh = __uint_as_float(hi << 16);
    float oh = __uint_as_float(hi & 0xffff0000u);
    lo = pack_bf16x2(e - eh, o - oh);
}

// ---------------- RoPE on q only (in place) ---------------------------------------
__global__ void rope_q_kernel(float* __restrict__ q,
                              const float* __restrict__ cs, const float* __restrict__ sn) {
    int idx = blockIdx.x * blockDim.x + threadIdx.x;    // B*T*NH*32 pairs
    if (idx >= 2 * TSEQ * NH * 32) return;
    int d2 = idx & 31;
    int h  = (idx >> 5) & 15;
    int tt = (idx >> 9) & (TSEQ - 1);
    int b  = idx >> 20;
    float c = cs[tt * 32 + d2], s = sn[tt * 32 + d2];
    size_t off = ((size_t)(b * TSEQ + tt)) * DIM + h * HD + d2 * 2;
    float e = q[off], o = q[off + 1];
    q[off] = e * c - o * s; q[off + 1] = e * s + o * c;
}

// ------- convert K (rope + split-bf16) and V (split-bf16, transposed) ------------
// grid: (32 keytiles, 32 bh); block 256
__global__ void convert_kv_kernel(const float* __restrict__ kb, const float* __restrict__ vb,
                                  const float* __restrict__ cs, const float* __restrict__ sn) {
    __shared__ uint32_t vh_s[64 * 33], vl_s[64 * 33];
    int jb = blockIdx.x * 64;
    int bh = blockIdx.y;
    int b = bh >> 4, h = bh & 15;
    int tid = threadIdx.x;

    // K: rope + split, layout [bh][key][dpair(32)]
    for (int i = tid; i < 64 * 16; i += 256) {
        int c4 = i & 15, key = i >> 4;
        int tt = jb + key;
        size_t g = ((size_t)(b * TSEQ + tt)) * DIM + h * HD + c4 * 4;
        float4 kv = *(const float4*)(kb + g);
        int d2a = 2 * c4, d2b = 2 * c4 + 1;
        float ca = cs[tt * 32 + d2a], sa = sn[tt * 32 + d2a];
        float cb = cs[tt * 32 + d2b], sb_ = sn[tt * 32 + d2b];
        float e0 = kv.x * ca - kv.y * sa, o0 = kv.x * sa + kv.y * ca;
        float e1 = kv.z * cb - kv.w * sb_, o1 = kv.z * sb_ + kv.w * cb;
        uint32_t h0, l0, h1, l1;
        split_bf16x2(e0, o0, h0, l0);
        split_bf16x2(e1, o1, h1, l1);
        size_t base = ((size_t)bh * TSEQ + tt) * 32 + 2 * c4;
        *(uint2*)&g_khi[base] = make_uint2(h0, h1);
        *(uint2*)&g_klo[base] = make_uint2(l0, l1);
    }

    // V: split + transpose via smem, out layout [bh][d(64)][keypair(1024)]
    for (int i = tid; i < 64 * 32; i += 256) {
        int d = i & 63, kp = i >> 6;
        size_t gbase = ((size_t)(b * TSEQ + jb + 2 * kp)) * DIM + h * HD + d;
        float v0 = vb[gbase], v1 = vb[gbase + DIM];
        uint32_t hh, ll;
        split_bf16x2(v0, v1, hh, ll);
        vh_s[d * 33 + kp] = hh;
        vl_s[d * 33 + kp] = ll;
    }
    __syncthreads();
    for (int j = tid; j < 64 * 32; j += 256) {
        int kp = j & 31, d = j >> 5;
        size_t out = ((size_t)bh * HD + d) * (TSEQ / 2) + (jb >> 1) + kp;
        g_vhi[out] = vh_s[d * 33 + kp];
        g_vlo[out] = vl_s[d * 33 + kp];
    }
}

// ---------- split-bf16 (3xBF16, m16n8k16) tensor-core flash attention -------------
__device__ __forceinline__ void mma_bf16(float* d, const uint32_t* a, const uint32_t* b) {
    asm volatile("mma.sync.aligned.m16n8k16.row.col.f32.bf16.bf16.f32 "
        "{%0,%1,%2,%3}, {%4,%5,%6,%7}, {%8,%9}, {%0,%1,%2,%3};\n"
        : "+f"(d[0]), "+f"(d[1]), "+f"(d[2]), "+f"(d[3])
        : "r"(a[0]), "r"(a[1]), "r"(a[2]), "r"(a[3]), "r"(b[0]), "r"(b[1]));
}

#define KVP 36   // word stride (pairs) for K and V^T smem rows

// grid: (16 qtiles reversed, 32 bh); block 256 (8 warps x 16 query rows)
__global__ __launch_bounds__(256)
void attn_mma_kernel(const float* __restrict__ qb, float* __restrict__ ob) {
    __shared__ uint32_t Kh[64 * KVP], Kl[64 * KVP], Vh[64 * KVP], Vl[64 * KVP];

    int qt = (int)gridDim.x - 1 - (int)blockIdx.x;   // heavy tiles first
    int bh = blockIdx.y;
    int b = bh >> 4;
    int h = bh & 15;
    int tid = threadIdx.x, w = tid >> 5, lane = tid & 31;
    int gid = lane >> 2, tig = lane & 3;
    int qrow0 = qt * 128 + w * 16;

    uint32_t qh[4][4], ql[4][4];
    const float* qbase = qb + ((size_t)(b * TSEQ + qrow0)) * DIM + h * HD;
    #pragma unroll
    for (int ks = 0; ks < 4; ks++) {
        int d0 = ks * 16 + 2 * tig;
        split_bf16x2(0.125f * qbase[(size_t)gid * DIM + d0],
                     0.125f * qbase[(size_t)gid * DIM + d0 + 1], qh[ks][0], ql[ks][0]);
        split_bf16x2(0.125f * qbase[(size_t)(gid + 8) * DIM + d0],
                     0.125f * qbase[(size_t)(gid + 8) * DIM + d0 + 1], qh[ks][1], ql[ks][1]);
        split_bf16x2(0.125f * qbase[(size_t)gid * DIM + d0 + 8],
                     0.125f * qbase[(size_t)gid * DIM + d0 + 9], qh[ks][2], ql[ks][2]);
        split_bf16x2(0.125f * qbase[(size_t)(gid + 8) * DIM + d0 + 8],
                     0.125f * qbase[(size_t)(gid + 8) * DIM + d0 + 9], qh[ks][3], ql[ks][3]);
    }

    float o[8][4];
    #pragma unroll
    for (int d = 0; d < 8; d++)
        #pragma unroll
        for (int j = 0; j < 4; j++) o[d][j] = 0.f;
    float mA = -1e30f, mB = -1e30f, lA = 0.f, lB = 0.f;

    const uint32_t* khiB = g_khi + (size_t)bh * TSEQ * 32;
    const uint32_t* kloB = g_klo + (size_t)bh * TSEQ * 32;
    const uint32_t* vhiB = g_vhi + (size_t)bh * HD * (TSEQ / 2);
    const uint32_t* vloB = g_vlo + (size_t)bh * HD * (TSEQ / 2);

    int ntiles = 2 * qt + 2;
    for (int kt = 0; kt < ntiles; kt++) {
        int jb = kt * 64;
        // fill K/V tile from pre-converted buffers (uint4 copies)
        for (int i = tid; i < 64 * 8; i += 256) {
            int c = i & 7, key = i >> 3;
            *(uint4*)&Kh[key * KVP + c * 4] = *(const uint4*)&khiB[(size_t)(jb + key) * 32 + c * 4];
            *(uint4*)&Kl[key * KVP + c * 4] = *(const uint4*)&kloB[(size_t)(jb + key) * 32 + c * 4];
            *(uint4*)&Vh[key * KVP + c * 4] = *(const uint4*)&vhiB[(size_t)key * (TSEQ / 2) + (jb >> 1) + c * 4];
            *(uint4*)&Vl[key * KVP + c * 4] = *(const uint4*)&vloB[(size_t)key * (TSEQ / 2) + (jb >> 1) + c * 4];
        }
        __syncthreads();

        if (jb <= qrow0 + 15) {   // tile has at least one unmasked key for this warp
            float sc[8][4];
            #pragma unroll
            for (int ch = 0; ch < 8; ch++) {
                sc[ch][0] = sc[ch][1] = sc[ch][2] = sc[ch][3] = 0.f;
                int krow = (ch * 8 + gid) * KVP;
                #pragma unroll
                for (int ks = 0; ks < 4; ks++) {
                    uint32_t bh_[2], bl_[2];
                    bh_[0] = Kh[krow + 8 * ks + tig]; bh_[1] = Kh[krow + 8 * ks + tig + 4];
                    bl_[0] = Kl[krow + 8 * ks + tig]; bl_[1] = Kl[krow + 8 * ks + tig + 4];
                    mma_bf16(sc[ch], qh[ks], bl_);
                    mma_bf16(sc[ch], ql[ks], bh_);
                    mma_bf16(sc[ch], qh[ks], bh_);
                }
            }

            if (jb + 63 > qrow0) {   // diagonal tile for this warp
                int qiA = qrow0 + gid, qiB = qrow0 + gid + 8;
                #pragma unroll
                for (int ch = 0; ch < 8; ch++) {
                    int j0 = jb + ch * 8 + 2 * tig;
                    if (j0     > qiA) sc[ch][0] = -1e30f;
                    if (j0 + 1 > qiA) sc[ch][1] = -1e30f;
                    if (j0     > qiB) sc[ch][2] = -1e30f;
                    if (j0 + 1 > qiB) sc[ch][3] = -1e30f;
                }
            }

            float tA = -1e30f, tB = -1e30f;
            #pragma unroll
            for (int ch = 0; ch < 8; ch++) {
                tA = fmaxf(tA, fmaxf(sc[ch][0], sc[ch][1]));
                tB = fmaxf(tB, fmaxf(sc[ch][2], sc[ch][3]));
            }
            tA = fmaxf(tA, __shfl_xor_sync(0xffffffffu, tA, 1));
            tA = fmaxf(tA, __shfl_xor_sync(0xffffffffu, tA, 2));
            tB = fmaxf(tB, __shfl_xor_sync(0xffffffffu, tB, 1));
            tB = fmaxf(tB, __shfl_xor_sync(0xffffffffu, tB, 2));
            float mAn = fmaxf(mA, tA), mBn = fmaxf(mB, tB);
            float corrA = __expf(mA - mAn), corrB = __expf(mB - mBn);
            mA = mAn; mB = mBn;

            float sumA = 0.f, sumB = 0.f;
            #pragma unroll
            for (int ch = 0; ch < 8; ch++) {
                sc[ch][0] = __expf(sc[ch][0] - mA);
                sc[ch][1] = __expf(sc[ch][1] - mA);
                sc[ch][2] = __expf(sc[ch][2] - mB);
                sc[ch][3] = __expf(sc[ch][3] - mB);
                sumA += sc[ch][0] + sc[ch][1];
                sumB += sc[ch][2] + sc[ch][3];
            }
            sumA += __shfl_xor_sync(0xffffffffu, sumA, 1);
            sumA += __shfl_xor_sync(0xffffffffu, sumA, 2);
            sumB += __shfl_xor_sync(0xffffffffu, sumB, 1);
            sumB += __shfl_xor_sync(0xffffffffu, sumB, 2);
            lA = lA * corrA + sumA;
            lB = lB * corrB + sumB;
            #pragma unroll
            for (int d = 0; d < 8; d++) {
                o[d][0] *= corrA; o[d][1] *= corrA;
                o[d][2] *= corrB; o[d][3] *= corrB;
            }

            #pragma unroll
            for (int kk = 0; kk < 4; kk++) {
                uint32_t ah_[4], al_[4];
                split_bf16x2(sc[2 * kk][0],     sc[2 * kk][1],     ah_[0], al_[0]);
                split_bf16x2(sc[2 * kk][2],     sc[2 * kk][3],     ah_[1], al_[1]);
                split_bf16x2(sc[2 * kk + 1][0], sc[2 * kk + 1][1], ah_[2], al_[2]);
                split_bf16x2(sc[2 * kk + 1][2], sc[2 * kk + 1][3], ah_[3], al_[3]);
                #pragma unroll
                for (int dc = 0; dc < 8; dc++) {
                    int vrow = (dc * 8 + gid) * KVP;
                    uint32_t bh_[2], bl_[2];
                    bh_[0] = Vh[vrow + 8 * kk + tig]; bh_[1] = Vh[vrow + 8 * kk + tig + 4];
                    bl_[0] = Vl[vrow + 8 * kk + tig]; bl_[1] = Vl[vrow + 8 * kk + tig + 4];
                    mma_bf16(o[dc], ah_, bl_);
                    mma_bf16(o[dc], al_, bh_);
                    mma_bf16(o[dc], ah_, bh_);
                }
            }
        }
        __syncthreads();
    }

    float invA = 1.f / lA, invB = 1.f / lB;
    float* obase = ob + ((size_t)(b * TSEQ + qrow0)) * DIM + h * HD;
    #pragma unroll
    for (int dc = 0; dc < 8; dc++) {
        *(float2*)&obase[(size_t)gid * DIM + dc * 8 + 2 * tig] =
            make_float2(o[dc][0] * invA, o[dc][1] * invA);
        *(float2*)&obase[(size_t)(gid + 8) * DIM + dc * 8 + 2 * tig] =
            make_float2(o[dc][2] * invB, o[dc][3] * invB);
    }
}

// ---------------- launch ----------------------------------------------------------
extern "C" void kernel_launch(void* const* d_in, const int* in_sizes, int n_in,
                              void* d_out, int out_size) {
    const float* x    = (const float*)d_in[0];
    const float* cosp = (const float*)d_in[1];
    const float* sinp = (const float*)d_in[2];
    const float* wq_w = (const float*)d_in[3];
    const float* wk_w = (const float*)d_in[4];
    const float* wv_w = (const float*)d_in[5];
    const float* wo_w = (const float*)d_in[6];
    float* out = (float*)d_out;

    void* p;
    cudaGetSymbolAddress(&p, g_wi); int8_t* wip = (int8_t*)p;
    cudaGetSymbolAddress(&p, g_ws); float*  wsp = (float*)p;
    cudaGetSymbolAddress(&p, g_xi); int8_t* xip = (int8_t*)p;
    cudaGetSymbolAddress(&p, g_sx); float*  sxp = (float*)p;
    cudaGetSymbolAddress(&p, g_q);  float*  qp  = (float*)p;
    cudaGetSymbolAddress(&p, g_k);  float*  kp  = (float*)p;
    cudaGetSymbolAddress(&p, g_v);  float*  vp  = (float*)p;
    cudaGetSymbolAddress(&p, g_ao); float*  aop = (float*)p;

    cudaFuncSetAttribute(gemm_i8mma_kernel, cudaFuncAttributeMaxDynamicSharedMemorySize, SMEM_GEMM);

    quant_w_kernel<<<4 * DIM * 8, 128>>>(wq_w, wk_w, wv_w, wo_w);
    quant_x_kernel<<<BT, 256>>>(x, xip, sxp);

    dim3 gq(DIM / 128, BT / 128, 3);
    gemm_i8mma_kernel<<<gq, 256, SMEM_GEMM>>>(xip, wip, wsp, sxp, qp, kp, vp);

    int npairs = 2 * TSEQ * NH * 32;
    rope_q_kernel<<<(npairs + 255) / 256, 256>>>(qp, cosp, sinp);
    convert_kv_kernel<<<dim3(TSEQ / 64, 2 * NH), 256>>>(kp, vp, cosp, sinp);

    attn_mma_kernel<<<dim3(TSEQ / 128, 2 * NH), 256>>>(qp, aop);

    quant_x_kernel<<<BT, 256>>>(aop, xip, sxp);
    dim3 go(DIM / 128, BT / 128, 1);
    gemm_i8mma_kernel<<<go, 256, SMEM_GEMM>>>(xip, wip + 3 * (size_t)DIM * DIM,
                                              wsp + 3 * DIM * 8, sxp, out, out, out);
}

// round 12
// speedup vs baseline: 1.0361x; 1.0361x over previous
#include <cuda_runtime.h>
#include <cuda_bf16.h>
#include <cstdint>

#define DIM 1024
#define NH 16
#define HD 64
#define BT 4096            // B*T tokens
#define TSEQ 2048
#define GROUP 128

// ---------------- scratch (device globals; no allocation allowed) ----------------
__device__ int8_t g_wi[4 * DIM * DIM];   // ternary weights as int8: q,k,v,o
__device__ float  g_ws[4 * DIM * 8];     // per-(matrix,row,group) scales
__device__ int8_t g_xi[BT * DIM];        // int8 activations (reused)
__device__ float  g_sx[BT];              // per-token 1/s (dequant scale)
__device__ float  g_q [BT * DIM];
__device__ float  g_k [BT * DIM];
__device__ float  g_v [BT * DIM];
__device__ float  g_ao[BT * DIM];        // attention output

// ---------------- weight quantization: per-(row,group) ternary -> int8 -----------
__global__ void quant_w_kernel(const float* __restrict__ w0, const float* __restrict__ w1,
                               const float* __restrict__ w2, const float* __restrict__ w3) {
    int blk = blockIdx.x;
    int g   = blk & 7;
    int row = (blk >> 3) & (DIM - 1);
    int m   = blk >> 13;
    const float* w = (m == 0) ? w0 : (m == 1) ? w1 : (m == 2) ? w2 : w3;
    int base = row * DIM + g * GROUP;
    float v = w[base + threadIdx.x];
    float a = fabsf(v);
    #pragma unroll
    for (int o = 16; o; o >>= 1) a += __shfl_xor_sync(0xffffffffu, a, o);
    __shared__ float sh[4];
    if ((threadIdx.x & 31) == 0) sh[threadIdx.x >> 5] = a;
    __syncthreads();
    float ws = (sh[0] + sh[1] + sh[2] + sh[3]) * (1.0f / GROUP) + 1e-5f;
    float q = fminf(fmaxf(rintf(v / ws), -1.f), 1.f);
    g_wi[m * (DIM * DIM) + base + threadIdx.x] = (int8_t)q;
    if (threadIdx.x == 0) g_ws[(m * DIM + row) * 8 + g] = ws;
}

// ---------------- activation quantization: per-token absmax -> int8 --------------
__global__ void quant_x_kernel(const float* __restrict__ x, int8_t* __restrict__ xi,
                               float* __restrict__ sx) {
    int tkn = blockIdx.x;
    const float* xr = x + (size_t)tkn * DIM;
    float mx = 0.f;
    for (int i = threadIdx.x; i < DIM; i += 256) mx = fmaxf(mx, fabsf(xr[i]));
    #pragma unroll
    for (int o = 16; o; o >>= 1) mx = fmaxf(mx, __shfl_xor_sync(0xffffffffu, mx, o));
    __shared__ float sh[8];
    if ((threadIdx.x & 31) == 0) sh[threadIdx.x >> 5] = mx;
    __syncthreads();
    float m = sh[0];
    #pragma unroll
    for (int i = 1; i < 8; i++) m = fmaxf(m, sh[i]);
    float s = 127.f / (m + 1e-5f);
    for (int i = threadIdx.x; i < DIM; i += 256) {
        float v = xr[i];
        xi[(size_t)tkn * DIM + i] = (int8_t)fminf(fmaxf(rintf(v * s), -128.f), 127.f);
    }
    if (threadIdx.x == 0) sx[tkn] = 1.0f / s;
}

// ---------------- int8 tensor-core GEMM: ldmatrix + cp.async double buffer --------
__device__ __forceinline__ void mma_s8(int* d, const int* a, const int* b) {
    asm volatile("mma.sync.aligned.m16n8k32.row.col.s32.s8.s8.s32 "
        "{%0,%1,%2,%3}, {%4,%5,%6,%7}, {%8,%9}, {%0,%1,%2,%3};\n"
        : "+r"(d[0]), "+r"(d[1]), "+r"(d[2]), "+r"(d[3])
        : "r"(a[0]), "r"(a[1]), "r"(a[2]), "r"(a[3]), "r"(b[0]), "r"(b[1]));
}
__device__ __forceinline__ void ldsm4(int& r0, int& r1, int& r2, int& r3, uint32_t addr) {
    asm volatile("ldmatrix.sync.aligned.m8n8.x4.shared.b16 {%0,%1,%2,%3}, [%4];"
        : "=r"(r0), "=r"(r1), "=r"(r2), "=r"(r3) : "r"(addr));
}
__device__ __forceinline__ void cp_async16(uint32_t s, const void* g) {
    asm volatile("cp.async.cg.shared.global [%0], [%1], 16;" :: "r"(s), "l"(g) : "memory");
}

#define GPAD 144
#define GBUF (128 * GPAD)
#define SMEM_GEMM (4 * GBUF + 8 * 128 * 4)

__global__ __launch_bounds__(256, 1)
void gemm_i8mma_kernel(const int8_t* __restrict__ Xi, const int8_t* __restrict__ WiB,
                       const float* __restrict__ wsB, const float* __restrict__ sx,
                       float* __restrict__ C0, float* __restrict__ C1, float* __restrict__ C2) {
    extern __shared__ int8_t smem[];
    int8_t* As = smem;
    int8_t* Bs = smem + 2 * GBUF;
    float*  wss = (float*)(smem + 4 * GBUF);
    uint32_t sA = (uint32_t)__cvta_generic_to_shared(As);
    uint32_t sB = (uint32_t)__cvta_generic_to_shared(Bs);

    int z = blockIdx.z;
    const int8_t* Wi = WiB + (size_t)z * DIM * DIM;
    const float*  ws = wsB + z * DIM * 8;
    float* C = (z == 0) ? C0 : (z == 1) ? C1 : C2;

    int t = threadIdx.x;
    int rowBlk = blockIdx.y * 128;
    int colBlk = blockIdx.x * 128;
    int warpId = t >> 5, lane = t & 31;
    int gid = lane >> 2, tig = lane & 3;
    int wm = (warpId >> 2) * 64;
    int wn = (warpId & 3) * 32;

    for (int i = t; i < 8 * 128; i += 256) {
        int col = i & 127, g = i >> 7;
        wss[g * 128 + col] = ws[(colBlk + col) * 8 + g];
    }

    int sel = lane >> 3;
    uint32_t aOff = (uint32_t)((wm + (sel & 1) * 8 + (lane & 7)) * GPAD + (sel >> 1) * 16);
    uint32_t bOff = (uint32_t)((wn + (sel >> 1) * 8 + (lane & 7)) * GPAD + (sel & 1) * 16);

    int   iacc[4][4][4];
    float facc[4][4][4];
    #pragma unroll
    for (int mt = 0; mt < 4; mt++)
        #pragma unroll
        for (int nt = 0; nt < 4; nt++)
            #pragma unroll
            for (int r = 0; r < 4; r++) { iacc[mt][nt][r] = 0; facc[mt][nt][r] = 0.f; }

    {
        #pragma unroll
        for (int r = 0; r < 4; r++) {
            int u = t + 256 * r;
            int row = u >> 3, c = u & 7;
            cp_async16(sA + row * GPAD + c * 16,
                       Xi + (size_t)(rowBlk + row) * DIM + c * 16);
            cp_async16(sB + row * GPAD + c * 16,
                       Wi + (size_t)(colBlk + row) * DIM + c * 16);
        }
        asm volatile("cp.async.commit_group;" ::: "memory");
    }

    for (int g = 0; g < 8; g++) {
        asm volatile("cp.async.wait_group 0;" ::: "memory");
        __syncthreads();
        if (g < 7) {
            int k0 = (g + 1) * GROUP;
            uint32_t dst = ((g + 1) & 1) * GBUF;
            #pragma unroll
            for (int r = 0; r < 4; r++) {
                int u = t + 256 * r;
                int row = u >> 3, c = u & 7;
                cp_async16(sA + dst + row * GPAD + c * 16,
                           Xi + (size_t)(rowBlk + row) * DIM + k0 + c * 16);
                cp_async16(sB + dst + row * GPAD + c * 16,
                           Wi + (size_t)(colBlk + row) * DIM + k0 + c * 16);
            }
            asm volatile("cp.async.commit_group;" ::: "memory");
        }

        uint32_t bufA = sA + (g & 1) * GBUF + aOff;
        uint32_t bufB = sB + (g & 1) * GBUF + bOff;
        #pragma unroll
        for (int ks = 0; ks < 4; ks++) {
            int a[4][4], b[4][2];
            #pragma unroll
            for (int mt = 0; mt < 4; mt++)
                ldsm4(a[mt][0], a[mt][1], a[mt][2], a[mt][3],
                      bufA + mt * 16 * GPAD + ks * 32);
            #pragma unroll
            for (int ntp = 0; ntp < 2; ntp++)
                ldsm4(b[2 * ntp][0], b[2 * ntp][1], b[2 * ntp + 1][0], b[2 * ntp + 1][1],
                      bufB + ntp * 16 * GPAD + ks * 32);
            #pragma unroll
            for (int mt = 0; mt < 4; mt++)
                #pragma unroll
                for (int nt = 0; nt < 4; nt++)
                    mma_s8(iacc[mt][nt], a[mt], b[nt]);
        }

        #pragma unroll
        for (int nt = 0; nt < 4; nt++) {
            float w0 = wss[g * 128 + wn + nt * 8 + 2 * tig];
            float w1 = wss[g * 128 + wn + nt * 8 + 2 * tig + 1];
            #pragma unroll
            for (int mt = 0; mt < 4; mt++) {
                facc[mt][nt][0] += w0 * (float)iacc[mt][nt][0]; iacc[mt][nt][0] = 0;
                facc[mt][nt][1] += w1 * (float)iacc[mt][nt][1]; iacc[mt][nt][1] = 0;
                facc[mt][nt][2] += w0 * (float)iacc[mt][nt][2]; iacc[mt][nt][2] = 0;
                facc[mt][nt][3] += w1 * (float)iacc[mt][nt][3]; iacc[mt][nt][3] = 0;
            }
        }
    }

    #pragma unroll
    for (int mt = 0; mt < 4; mt++) {
        int row0 = rowBlk + wm + mt * 16 + gid;
        float s0 = sx[row0], s1 = sx[row0 + 8];
        #pragma unroll
        for (int nt = 0; nt < 4; nt++) {
            int col = colBlk + wn + nt * 8 + 2 * tig;
            *(float2*)&C[(size_t)row0 * DIM + col] =
                make_float2(facc[mt][nt][0] * s0, facc[mt][nt][1] * s0);
            *(float2*)&C[(size_t)(row0 + 8) * DIM + col] =
                make_float2(facc[mt][nt][2] * s1, facc[mt][nt][3] * s1);
        }
    }
}

// ---------------- RoPE on k only (in place; q handled inside attention) -----------
__global__ void rope_k_kernel(float* __restrict__ k,
                              const float* __restrict__ cs, const float* __restrict__ sn) {
    int idx = blockIdx.x * blockDim.x + threadIdx.x;    // B*T*NH*32 pairs
    if (idx >= 2 * TSEQ * NH * 32) return;
    int d2 = idx & 31;
    int h  = (idx >> 5) & 15;
    int tt = (idx >> 9) & (TSEQ - 1);
    int b  = idx >> 20;
    float c = cs[tt * 32 + d2], s = sn[tt * 32 + d2];
    size_t off = ((size_t)(b * TSEQ + tt)) * DIM + h * HD + d2 * 2;
    float e = k[off], o = k[off + 1];
    k[off] = e * c - o * s; k[off + 1] = e * s + o * c;
}

// ---------- split-bf16 (3xBF16, m16n8k16) tensor-core flash attention -------------
__device__ __forceinline__ uint32_t pack_bf16x2(float e, float o) {
    uint32_t r; asm("cvt.rn.bf16x2.f32 %0, %1, %2;" : "=r"(r) : "f"(o), "f"(e)); return r;
}
__device__ __forceinline__ void split_bf16x2(float e, float o, uint32_t& hi, uint32_t& lo) {
    hi = pack_bf16x2(e, o);
    float eh = __uint_as_float(hi << 16);
    float oh = __uint_as_float(hi & 0xffff0000u);
    lo = pack_bf16x2(e - eh, o - oh);
}
__device__ __forceinline__ void mma_bf16(float* d, const uint32_t* a, const uint32_t* b) {
    asm volatile("mma.sync.aligned.m16n8k16.row.col.f32.bf16.bf16.f32 "
        "{%0,%1,%2,%3}, {%4,%5,%6,%7}, {%8,%9}, {%0,%1,%2,%3};\n"
        : "+f"(d[0]), "+f"(d[1]), "+f"(d[2]), "+f"(d[3])
        : "r"(a[0]), "r"(a[1]), "r"(a[2]), "r"(a[3]), "r"(b[0]), "r"(b[1]));
}

#define KVP 36   // word stride (pairs) for K and V^T smem rows

// load q pair (d0, d0+1) for token tt, apply rope, scale by 0.125, split to bf16 hi/lo
__device__ __forceinline__ void q_rope_split(const float* __restrict__ qrow, int tt, int d2,
                                             const float* __restrict__ cs,
                                             const float* __restrict__ sn,
                                             uint32_t& hi, uint32_t& lo) {
    float e = qrow[2 * d2], o = qrow[2 * d2 + 1];
    float c = cs[tt * 32 + d2], s = sn[tt * 32 + d2];
    float re = e * c - o * s;
    float ro = e * s + o * c;
    split_bf16x2(0.125f * re, 0.125f * ro, hi, lo);
}

// grid: (32 qtiles reversed, 32 bh); block 128 (4 warps x 16 query rows)
__global__ __launch_bounds__(128)
void attn_mma_kernel(const float* __restrict__ qb, const float* __restrict__ kb,
                     const float* __restrict__ vb, float* __restrict__ ob,
                     const float* __restrict__ cs, const float* __restrict__ sn) {
    __shared__ uint32_t Kh[64 * KVP], Kl[64 * KVP], Vh[64 * KVP], Vl[64 * KVP];

    int qtile = (int)gridDim.x - 1 - (int)blockIdx.x;   // heavy tiles first
    int bh = blockIdx.y;
    int b = bh >> 4, h = bh & 15;
    int tid = threadIdx.x, w = tid >> 5, lane = tid & 31;
    int gid = lane >> 2, tig = lane & 3;
    int qrow0 = qtile * 64 + w * 16;

    // Q fragments with fused rope: qh/ql[ks][4]
    uint32_t qh[4][4], ql[4][4];
    const float* qrowA = qb + ((size_t)(b * TSEQ + qrow0 + gid)) * DIM + h * HD;
    const float* qrowB = qrowA + 8 * DIM;
    int ttA = qrow0 + gid, ttB = ttA + 8;
    #pragma unroll
    for (int ks = 0; ks < 4; ks++) {
        int d2a = ks * 8 + tig;          // pair index for d0 = ks*16 + 2*tig
        q_rope_split(qrowA, ttA, d2a,     cs, sn, qh[ks][0], ql[ks][0]);
        q_rope_split(qrowB, ttB, d2a,     cs, sn, qh[ks][1], ql[ks][1]);
        q_rope_split(qrowA, ttA, d2a + 4, cs, sn, qh[ks][2], ql[ks][2]);
        q_rope_split(qrowB, ttB, d2a + 4, cs, sn, qh[ks][3], ql[ks][3]);
    }

    float o[8][4];
    #pragma unroll
    for (int d = 0; d < 8; d++)
        #pragma unroll
        for (int j = 0; j < 4; j++) o[d][j] = 0.f;
    float mA = -1e30f, mB = -1e30f, lA = 0.f, lB = 0.f;

    int ntiles = qtile + 1;
    for (int kt = 0; kt < ntiles; kt++) {
        int jb = kt * 64;
        for (int i = tid; i < 64 * 16; i += 128) {
            int c4 = i & 15, key = i >> 4;
            float4 kv = *(const float4*)(kb + ((size_t)(b * TSEQ + jb + key)) * DIM + h * HD + c4 * 4);
            uint32_t h0, l0, h1, l1;
            split_bf16x2(kv.x, kv.y, h0, l0);
            split_bf16x2(kv.z, kv.w, h1, l1);
            Kh[key * KVP + 2 * c4] = h0; Kh[key * KVP + 2 * c4 + 1] = h1;
            Kl[key * KVP + 2 * c4] = l0; Kl[key * KVP + 2 * c4 + 1] = l1;
        }
        for (int i = tid; i < 64 * 32; i += 128) {
            int d = i & 63, kp = i >> 6;
            size_t gbase = ((size_t)(b * TSEQ + jb + 2 * kp)) * DIM + h * HD + d;
            float v0 = vb[gbase], v1 = vb[gbase + DIM];
            uint32_t hh, ll;
            split_bf16x2(v0, v1, hh, ll);
            Vh[d * KVP + kp] = hh;
            Vl[d * KVP + kp] = ll;
        }
        __syncthreads();

        float sc[8][4];
        #pragma unroll
        for (int ch = 0; ch < 8; ch++) {
            sc[ch][0] = sc[ch][1] = sc[ch][2] = sc[ch][3] = 0.f;
            int krow = (ch * 8 + gid) * KVP;
            #pragma unroll
            for (int ks = 0; ks < 4; ks++) {
                uint32_t bh_[2], bl_[2];
                bh_[0] = Kh[krow + 8 * ks + tig]; bh_[1] = Kh[krow + 8 * ks + tig + 4];
                bl_[0] = Kl[krow + 8 * ks + tig]; bl_[1] = Kl[krow + 8 * ks + tig + 4];
                mma_bf16(sc[ch], qh[ks], bl_);
                mma_bf16(sc[ch], ql[ks], bh_);
                mma_bf16(sc[ch], qh[ks], bh_);
            }
        }

        if (kt == ntiles - 1) {
            int qiA = qrow0 + gid, qiB = qrow0 + gid + 8;
            #pragma unroll
            for (int ch = 0; ch < 8; ch++) {
                int j0 = jb + ch * 8 + 2 * tig;
                if (j0     > qiA) sc[ch][0] = -1e30f;
                if (j0 + 1 > qiA) sc[ch][1] = -1e30f;
                if (j0     > qiB) sc[ch][2] = -1e30f;
                if (j0 + 1 > qiB) sc[ch][3] = -1e30f;
            }
        }

        float tA = -1e30f, tB = -1e30f;
        #pragma unroll
        for (int ch = 0; ch < 8; ch++) {
            tA = fmaxf(tA, fmaxf(sc[ch][0], sc[ch][1]));
            tB = fmaxf(tB, fmaxf(sc[ch][2], sc[ch][3]));
        }
        tA = fmaxf(tA, __shfl_xor_sync(0xffffffffu, tA, 1));
        tA = fmaxf(tA, __shfl_xor_sync(0xffffffffu, tA, 2));
        tB = fmaxf(tB, __shfl_xor_sync(0xffffffffu, tB, 1));
        tB = fmaxf(tB, __shfl_xor_sync(0xffffffffu, tB, 2));
        float mAn = fmaxf(mA, tA), mBn = fmaxf(mB, tB);
        float corrA = __expf(mA - mAn), corrB = __expf(mB - mBn);
        mA = mAn; mB = mBn;

        float sumA = 0.f, sumB = 0.f;
        #pragma unroll
        for (int ch = 0; ch < 8; ch++) {
            sc[ch][0] = __expf(sc[ch][0] - mA);
            sc[ch][1] = __expf(sc[ch][1] - mA);
            sc[ch][2] = __expf(sc[ch][2] - mB);
            sc[ch][3] = __expf(sc[ch][3] - mB);
            sumA += sc[ch][0] + sc[ch][1];
            sumB += sc[ch][2] + sc[ch][3];
        }
        sumA += __shfl_xor_sync(0xffffffffu, sumA, 1);
        sumA += __shfl_xor_sync(0xffffffffu, sumA, 2);
        sumB += __shfl_xor_sync(0xffffffffu, sumB, 1);
        sumB += __shfl_xor_sync(0xffffffffu, sumB, 2);
        lA = lA * corrA + sumA;
        lB = lB * corrB + sumB;
        #pragma unroll
        for (int d = 0; d < 8; d++) {
            o[d][0] *= corrA; o[d][1] *= corrA;
            o[d][2] *= corrB; o[d][3] *= corrB;
        }

        #pragma unroll
        for (int kk = 0; kk < 4; kk++) {
            uint32_t ah_[4], al_[4];
            split_bf16x2(sc[2 * kk][0],     sc[2 * kk][1],     ah_[0], al_[0]);
            split_bf16x2(sc[2 * kk][2],     sc[2 * kk][3],     ah_[1], al_[1]);
            split_bf16x2(sc[2 * kk + 1][0], sc[2 * kk + 1][1], ah_[2], al_[2]);
            split_bf16x2(sc[2 * kk + 1][2], sc[2 * kk + 1][3], ah_[3], al_[3]);
            #pragma unroll
            for (int dc = 0; dc < 8; dc++) {
                int vrow = (dc * 8 + gid) * KVP;
                uint32_t bh_[2], bl_[2];
                bh_[0] = Vh[vrow + 8 * kk + tig]; bh_[1] = Vh[vrow + 8 * kk + tig + 4];
                bl_[0] = Vl[vrow + 8 * kk + tig]; bl_[1] = Vl[vrow + 8 * kk + tig + 4];
                mma_bf16(o[dc], ah_, bl_);
                mma_bf16(o[dc], al_, bh_);
                mma_bf16(o[dc], ah_, bh_);
            }
        }
        __syncthreads();
    }

    float invA = 1.f / lA, invB = 1.f / lB;
    float* obase = ob + ((size_t)(b * TSEQ + qrow0)) * DIM + h * HD;
    #pragma unroll
    for (int dc = 0; dc < 8; dc++) {
        *(float2*)&obase[(size_t)gid * DIM + dc * 8 + 2 * tig] =
            make_float2(o[dc][0] * invA, o[dc][1] * invA);
        *(float2*)&obase[(size_t)(gid + 8) * DIM + dc * 8 + 2 * tig] =
            make_float2(o[dc][2] * invB, o[dc][3] * invB);
    }
}

// ---------------- launch ----------------------------------------------------------
extern "C" void kernel_launch(void* const* d_in, const int* in_sizes, int n_in,
                              void* d_out, int out_size) {
    const float* x    = (const float*)d_in[0];
    const float* cosp = (const float*)d_in[1];
    const float* sinp = (const float*)d_in[2];
    const float* wq_w = (const float*)d_in[3];
    const float* wk_w = (const float*)d_in[4];
    const float* wv_w = (const float*)d_in[5];
    const float* wo_w = (const float*)d_in[6];
    float* out = (float*)d_out;

    void* p;
    cudaGetSymbolAddress(&p, g_wi); int8_t* wip = (int8_t*)p;
    cudaGetSymbolAddress(&p, g_ws); float*  wsp = (float*)p;
    cudaGetSymbolAddress(&p, g_xi); int8_t* xip = (int8_t*)p;
    cudaGetSymbolAddress(&p, g_sx); float*  sxp = (float*)p;
    cudaGetSymbolAddress(&p, g_q);  float*  qp  = (float*)p;
    cudaGetSymbolAddress(&p, g_k);  float*  kp  = (float*)p;
    cudaGetSymbolAddress(&p, g_v);  float*  vp  = (float*)p;
    cudaGetSymbolAddress(&p, g_ao); float*  aop = (float*)p;

    cudaFuncSetAttribute(gemm_i8mma_kernel, cudaFuncAttributeMaxDynamicSharedMemorySize, SMEM_GEMM);

    quant_w_kernel<<<4 * DIM * 8, 128>>>(wq_w, wk_w, wv_w, wo_w);
    quant_x_kernel<<<BT, 256>>>(x, xip, sxp);

    dim3 gq(DIM / 128, BT / 128, 3);
    gemm_i8mma_kernel<<<gq, 256, SMEM_GEMM>>>(xip, wip, wsp, sxp, qp, kp, vp);

    int npairs = 2 * TSEQ * NH * 32;
    rope_k_kernel<<<(npairs + 255) / 256, 256>>>(kp, cosp, sinp);

    attn_mma_kernel<<<dim3(TSEQ / 64, 2 * NH), 128>>>(qp, kp, vp, aop, cosp, sinp);

    quant_x_kernel<<<BT, 256>>>(aop, xip, sxp);
    dim3 go(DIM / 128, BT / 128, 1);
    gemm_i8mma_kernel<<<go, 256, SMEM_GEMM>>>(xip, wip + 3 * (size_t)DIM * DIM,
                                              wsp + 3 * DIM * 8, sxp, out, out, out);
}

// round 14
// speedup vs baseline: 1.0516x; 1.0150x over previous
#include <cuda_runtime.h>
#include <cuda_bf16.h>
#include <cstdint>

#define DIM 1024
#define NH 16
#define HD 64
#define BT 4096            // B*T tokens
#define TSEQ 2048
#define GROUP 128

// ---------------- scratch (device globals; no allocation allowed) ----------------
__device__ int8_t g_wi[4 * DIM * DIM];   // ternary weights as int8: q,k,v,o
__device__ float  g_ws[4 * DIM * 8];     // per-(matrix,row,group) scales
__device__ int8_t g_xi[BT * DIM];        // int8 activations (reused)
__device__ float  g_sx[BT];              // per-token 1/s (dequant scale)
__device__ float  g_q [BT * DIM];
__device__ float  g_k [BT * DIM];
__device__ float  g_v [BT * DIM];
__device__ float  g_ao[BT * DIM];        // attention output

// ---------------- weight quantization: per-(row,group) ternary -> int8 -----------
__global__ void quant_w_kernel(const float* __restrict__ w0, const float* __restrict__ w1,
                               const float* __restrict__ w2, const float* __restrict__ w3) {
    int blk = blockIdx.x;
    int g   = blk & 7;
    int row = (blk >> 3) & (DIM - 1);
    int m   = blk >> 13;
    const float* w = (m == 0) ? w0 : (m == 1) ? w1 : (m == 2) ? w2 : w3;
    int base = row * DIM + g * GROUP;
    float v = w[base + threadIdx.x];
    float a = fabsf(v);
    #pragma unroll
    for (int o = 16; o; o >>= 1) a += __shfl_xor_sync(0xffffffffu, a, o);
    __shared__ float sh[4];
    if ((threadIdx.x & 31) == 0) sh[threadIdx.x >> 5] = a;
    __syncthreads();
    float ws = (sh[0] + sh[1] + sh[2] + sh[3]) * (1.0f / GROUP) + 1e-5f;
    float q = fminf(fmaxf(rintf(v / ws), -1.f), 1.f);
    g_wi[m * (DIM * DIM) + base + threadIdx.x] = (int8_t)q;
    if (threadIdx.x == 0) g_ws[(m * DIM + row) * 8 + g] = ws;
}

// ---------------- activation quantization: per-token absmax -> int8 --------------
__global__ void quant_x_kernel(const float* __restrict__ x, int8_t* __restrict__ xi,
                               float* __restrict__ sx) {
    int tkn = blockIdx.x;
    const float* xr = x + (size_t)tkn * DIM;
    float mx = 0.f;
    for (int i = threadIdx.x; i < DIM; i += 256) mx = fmaxf(mx, fabsf(xr[i]));
    #pragma unroll
    for (int o = 16; o; o >>= 1) mx = fmaxf(mx, __shfl_xor_sync(0xffffffffu, mx, o));
    __shared__ float sh[8];
    if ((threadIdx.x & 31) == 0) sh[threadIdx.x >> 5] = mx;
    __syncthreads();
    float m = sh[0];
    #pragma unroll
    for (int i = 1; i < 8; i++) m = fmaxf(m, sh[i]);
    float s = 127.f / (m + 1e-5f);
    for (int i = threadIdx.x; i < DIM; i += 256) {
        float v = xr[i];
        xi[(size_t)tkn * DIM + i] = (int8_t)fminf(fmaxf(rintf(v * s), -128.f), 127.f);
    }
    if (threadIdx.x == 0) sx[tkn] = 1.0f / s;
}

// ------- int8 tensor-core GEMM: 512 threads, 16 warps (4m x 4n), warp tile 32x32 --
__device__ __forceinline__ void mma_s8(int* d, const int* a, const int* b) {
    asm volatile("mma.sync.aligned.m16n8k32.row.col.s32.s8.s8.s32 "
        "{%0,%1,%2,%3}, {%4,%5,%6,%7}, {%8,%9}, {%0,%1,%2,%3};\n"
        : "+r"(d[0]), "+r"(d[1]), "+r"(d[2]), "+r"(d[3])
        : "r"(a[0]), "r"(a[1]), "r"(a[2]), "r"(a[3]), "r"(b[0]), "r"(b[1]));
}
__device__ __forceinline__ void ldsm4(int& r0, int& r1, int& r2, int& r3, uint32_t addr) {
    asm volatile("ldmatrix.sync.aligned.m8n8.x4.shared.b16 {%0,%1,%2,%3}, [%4];"
        : "=r"(r0), "=r"(r1), "=r"(r2), "=r"(r3) : "r"(addr));
}
__device__ __forceinline__ void cp_async16(uint32_t s, const void* g) {
    asm volatile("cp.async.cg.shared.global [%0], [%1], 16;" :: "r"(s), "l"(g) : "memory");
}

#define GPAD 144
#define GBUF (128 * GPAD)
#define SMEM_GEMM (4 * GBUF + 8 * 128 * 4)

__global__ __launch_bounds__(512, 1)
void gemm_i8mma_kernel(const int8_t* __restrict__ Xi, const int8_t* __restrict__ WiB,
                       const float* __restrict__ wsB, const float* __restrict__ sx,
                       float* __restrict__ C0, float* __restrict__ C1, float* __restrict__ C2) {
    extern __shared__ int8_t smem[];
    int8_t* As = smem;
    int8_t* Bs = smem + 2 * GBUF;
    float*  wss = (float*)(smem + 4 * GBUF);
    uint32_t sA = (uint32_t)__cvta_generic_to_shared(As);
    uint32_t sB = (uint32_t)__cvta_generic_to_shared(Bs);

    int z = blockIdx.z;
    const int8_t* Wi = WiB + (size_t)z * DIM * DIM;
    const float*  ws = wsB + z * DIM * 8;
    float* C = (z == 0) ? C0 : (z == 1) ? C1 : C2;

    int t = threadIdx.x;
    int rowBlk = blockIdx.y * 128;
    int colBlk = blockIdx.x * 128;
    int warpId = t >> 5, lane = t & 31;
    int gid = lane >> 2, tig = lane & 3;
    int wm = (warpId >> 2) * 32;
    int wn = (warpId & 3) * 32;

    for (int i = t; i < 8 * 128; i += 512) {
        int col = i & 127, g = i >> 7;
        wss[g * 128 + col] = ws[(colBlk + col) * 8 + g];
    }

    int sel = lane >> 3;
    uint32_t aOff = (uint32_t)((wm + (sel & 1) * 8 + (lane & 7)) * GPAD + (sel >> 1) * 16);
    uint32_t bOff = (uint32_t)((wn + (sel >> 1) * 8 + (lane & 7)) * GPAD + (sel & 1) * 16);

    int   iacc[2][4][4];
    float facc[2][4][4];
    #pragma unroll
    for (int mt = 0; mt < 2; mt++)
        #pragma unroll
        for (int nt = 0; nt < 4; nt++)
            #pragma unroll
            for (int r = 0; r < 4; r++) { iacc[mt][nt][r] = 0; facc[mt][nt][r] = 0.f; }

    // issue copy of group 0 into buffer 0
    {
        #pragma unroll
        for (int r = 0; r < 2; r++) {
            int u = t + 512 * r;               // 0..1023
            int row = u >> 3, c = u & 7;
            cp_async16(sA + row * GPAD + c * 16,
                       Xi + (size_t)(rowBlk + row) * DIM + c * 16);
            cp_async16(sB + row * GPAD + c * 16,
                       Wi + (size_t)(colBlk + row) * DIM + c * 16);
        }
        asm volatile("cp.async.commit_group;" ::: "memory");
    }

    for (int g = 0; g < 8; g++) {
        asm volatile("cp.async.wait_group 0;" ::: "memory");
        __syncthreads();
        if (g < 7) {
            int k0 = (g + 1) * GROUP;
            uint32_t dst = ((g + 1) & 1) * GBUF;
            #pragma unroll
            for (int r = 0; r < 2; r++) {
                int u = t + 512 * r;
                int row = u >> 3, c = u & 7;
                cp_async16(sA + dst + row * GPAD + c * 16,
                           Xi + (size_t)(rowBlk + row) * DIM + k0 + c * 16);
                cp_async16(sB + dst + row * GPAD + c * 16,
                           Wi + (size_t)(colBlk + row) * DIM + k0 + c * 16);
            }
            asm volatile("cp.async.commit_group;" ::: "memory");
        }

        uint32_t bufA = sA + (g & 1) * GBUF + aOff;
        uint32_t bufB = sB + (g & 1) * GBUF + bOff;
        #pragma unroll
        for (int ks = 0; ks < 4; ks++) {
            int a[2][4], b[4][2];
            #pragma unroll
            for (int mt = 0; mt < 2; mt++)
                ldsm4(a[mt][0], a[mt][1], a[mt][2], a[mt][3],
                      bufA + mt * 16 * GPAD + ks * 32);
            #pragma unroll
            for (int ntp = 0; ntp < 2; ntp++)
                ldsm4(b[2 * ntp][0], b[2 * ntp][1], b[2 * ntp + 1][0], b[2 * ntp + 1][1],
                      bufB + ntp * 16 * GPAD + ks * 32);
            #pragma unroll
            for (int mt = 0; mt < 2; mt++)
                #pragma unroll
                for (int nt = 0; nt < 4; nt++)
                    mma_s8(iacc[mt][nt], a[mt], b[nt]);
        }

        #pragma unroll
        for (int nt = 0; nt < 4; nt++) {
            float w0 = wss[g * 128 + wn + nt * 8 + 2 * tig];
            float w1 = wss[g * 128 + wn + nt * 8 + 2 * tig + 1];
            #pragma unroll
            for (int mt = 0; mt < 2; mt++) {
                facc[mt][nt][0] += w0 * (float)iacc[mt][nt][0]; iacc[mt][nt][0] = 0;
                facc[mt][nt][1] += w1 * (float)iacc[mt][nt][1]; iacc[mt][nt][1] = 0;
                facc[mt][nt][2] += w0 * (float)iacc[mt][nt][2]; iacc[mt][nt][2] = 0;
                facc[mt][nt][3] += w1 * (float)iacc[mt][nt][3]; iacc[mt][nt][3] = 0;
            }
        }
    }

    #pragma unroll
    for (int mt = 0; mt < 2; mt++) {
        int row0 = rowBlk + wm + mt * 16 + gid;
        float s0 = sx[row0], s1 = sx[row0 + 8];
        #pragma unroll
        for (int nt = 0; nt < 4; nt++) {
            int col = colBlk + wn + nt * 8 + 2 * tig;
            *(float2*)&C[(size_t)row0 * DIM + col] =
                make_float2(facc[mt][nt][0] * s0, facc[mt][nt][1] * s0);
            *(float2*)&C[(size_t)(row0 + 8) * DIM + col] =
                make_float2(facc[mt][nt][2] * s1, facc[mt][nt][3] * s1);
        }
    }
}

// ---------------- RoPE on k only (in place; q handled inside attention) -----------
__global__ void rope_k_kernel(float* __restrict__ k,
                              const float* __restrict__ cs, const float* __restrict__ sn) {
    int idx = blockIdx.x * blockDim.x + threadIdx.x;
    if (idx >= 2 * TSEQ * NH * 32) return;
    int d2 = idx & 31;
    int h  = (idx >> 5) & 15;
    int tt = (idx >> 9) & (TSEQ - 1);
    int b  = idx >> 20;
    float c = cs[tt * 32 + d2], s = sn[tt * 32 + d2];
    size_t off = ((size_t)(b * TSEQ + tt)) * DIM + h * HD + d2 * 2;
    float e = k[off], o = k[off + 1];
    k[off] = e * c - o * s; k[off + 1] = e * s + o * c;
}

// ---------- split-bf16 (3xBF16, m16n8k16) tensor-core flash attention -------------
__device__ __forceinline__ uint32_t pack_bf16x2(float e, float o) {
    uint32_t r; asm("cvt.rn.bf16x2.f32 %0, %1, %2;" : "=r"(r) : "f"(o), "f"(e)); return r;
}
__device__ __forceinline__ void split_bf16x2(float e, float o, uint32_t& hi, uint32_t& lo) {
    hi = pack_bf16x2(e, o);
    float eh = __uint_as_float(hi << 16);
    float oh = __uint_as_float(hi & 0xffff0000u);
    lo = pack_bf16x2(e - eh, o - oh);
}
__device__ __forceinline__ void mma_bf16(float* d, const uint32_t* a, const uint32_t* b) {
    asm volatile("mma.sync.aligned.m16n8k16.row.col.f32.bf16.bf16.f32 "
        "{%0,%1,%2,%3}, {%4,%5,%6,%7}, {%8,%9}, {%0,%1,%2,%3};\n"
        : "+f"(d[0]), "+f"(d[1]), "+f"(d[2]), "+f"(d[3])
        : "r"(a[0]), "r"(a[1]), "r"(a[2]), "r"(a[3]), "r"(b[0]), "r"(b[1]));
}

#define KVP 36   // word stride (pairs) for K and V^T smem rows

__device__ __forceinline__ void q_rope_split(const float* __restrict__ qrow, int tt, int d2,
                                             const float* __restrict__ cs,
                                             const float* __restrict__ sn,
                                             uint32_t& hi, uint32_t& lo) {
    float e = qrow[2 * d2], o = qrow[2 * d2 + 1];
    float c = cs[tt * 32 + d2], s = sn[tt * 32 + d2];
    float re = e * c - o * s;
    float ro = e * s + o * c;
    split_bf16x2(0.125f * re, 0.125f * ro, hi, lo);
}

__global__ __launch_bounds__(128)
void attn_mma_kernel(const float* __restrict__ qb, const float* __restrict__ kb,
                     const float* __restrict__ vb, float* __restrict__ ob,
                     const float* __restrict__ cs, const float* __restrict__ sn) {
    __shared__ uint32_t Kh[64 * KVP], Kl[64 * KVP], Vh[64 * KVP], Vl[64 * KVP];

    int qtile = (int)gridDim.x - 1 - (int)blockIdx.x;   // heavy tiles first
    int bh = blockIdx.y;
    int b = bh >> 4, h = bh & 15;
    int tid = threadIdx.x, w = tid >> 5, lane = tid & 31;
    int gid = lane >> 2, tig = lane & 3;
    int qrow0 = qtile * 64 + w * 16;

    uint32_t qh[4][4], ql[4][4];
    const float* qrowA = qb + ((size_t)(b * TSEQ + qrow0 + gid)) * DIM + h * HD;
    const float* qrowB = qrowA + 8 * DIM;
    int ttA = qrow0 + gid, ttB = ttA + 8;
    #pragma unroll
    for (int ks = 0; ks < 4; ks++) {
        int d2a = ks * 8 + tig;
        q_rope_split(qrowA, ttA, d2a,     cs, sn, qh[ks][0], ql[ks][0]);
        q_rope_split(qrowB, ttB, d2a,     cs, sn, qh[ks][1], ql[ks][1]);
        q_rope_split(qrowA, ttA, d2a + 4, cs, sn, qh[ks][2], ql[ks][2]);
        q_rope_split(qrowB, ttB, d2a + 4, cs, sn, qh[ks][3], ql[ks][3]);
    }

    float o[8][4];
    #pragma unroll
    for (int d = 0; d < 8; d++)
        #pragma unroll
        for (int j = 0; j < 4; j++) o[d][j] = 0.f;
    float mA = -1e30f, mB = -1e30f, lA = 0.f, lB = 0.f;

    int ntiles = qtile + 1;
    for (int kt = 0; kt < ntiles; kt++) {
        int jb = kt * 64;
        for (int i = tid; i < 64 * 16; i += 128) {
            int c4 = i & 15, key = i >> 4;
            float4 kv = *(const float4*)(kb + ((size_t)(b * TSEQ + jb + key)) * DIM + h * HD + c4 * 4);
            uint32_t h0, l0, h1, l1;
            split_bf16x2(kv.x, kv.y, h0, l0);
            split_bf16x2(kv.z, kv.w, h1, l1);
            Kh[key * KVP + 2 * c4] = h0; Kh[key * KVP + 2 * c4 + 1] = h1;
            Kl[key * KVP + 2 * c4] = l0; Kl[key * KVP + 2 * c4 + 1] = l1;
        }
        for (int i = tid; i < 64 * 32; i += 128) {
            int d = i & 63, kp = i >> 6;
            size_t gbase = ((size_t)(b * TSEQ + jb + 2 * kp)) * DIM + h * HD + d;
            float v0 = vb[gbase], v1 = vb[gbase + DIM];
            uint32_t hh, ll;
            split_bf16x2(v0, v1, hh, ll);
            Vh[d * KVP + kp] = hh;
            Vl[d * KVP + kp] = ll;
        }
        __syncthreads();

        float sc[8][4];
        #pragma unroll
        for (int ch = 0; ch < 8; ch++) {
            sc[ch][0] = sc[ch][1] = sc[ch][2] = sc[ch][3] = 0.f;
            int krow = (ch * 8 + gid) * KVP;
            #pragma unroll
            for (int ks = 0; ks < 4; ks++) {
                uint32_t bh_[2], bl_[2];
                bh_[0] = Kh[krow + 8 * ks + tig]; bh_[1] = Kh[krow + 8 * ks + tig + 4];
                bl_[0] = Kl[krow + 8 * ks + tig]; bl_[1] = Kl[krow + 8 * ks + tig + 4];
                mma_bf16(sc[ch], qh[ks], bl_);
                mma_bf16(sc[ch], ql[ks], bh_);
                mma_bf16(sc[ch], qh[ks], bh_);
            }
        }

        if (kt == ntiles - 1) {
            int qiA = qrow0 + gid, qiB = qrow0 + gid + 8;
            #pragma unroll
            for (int ch = 0; ch < 8; ch++) {
                int j0 = jb + ch * 8 + 2 * tig;
                if (j0     > qiA) sc[ch][0] = -1e30f;
                if (j0 + 1 > qiA) sc[ch][1] = -1e30f;
                if (j0     > qiB) sc[ch][2] = -1e30f;
                if (j0 + 1 > qiB) sc[ch][3] = -1e30f;
            }
        }

        float tA = -1e30f, tB = -1e30f;
        #pragma unroll
        for (int ch = 0; ch < 8; ch++) {
            tA = fmaxf(tA, fmaxf(sc[ch][0], sc[ch][1]));
            tB = fmaxf(tB, fmaxf(sc[ch][2], sc[ch][3]));
        }
        tA = fmaxf(tA, __shfl_xor_sync(0xffffffffu, tA, 1));
        tA = fmaxf(tA, __shfl_xor_sync(0xffffffffu, tA, 2));
        tB = fmaxf(tB, __shfl_xor_sync(0xffffffffu, tB, 1));
        tB = fmaxf(tB, __shfl_xor_sync(0xffffffffu, tB, 2));
        float mAn = fmaxf(mA, tA), mBn = fmaxf(mB, tB);
        float corrA = __expf(mA - mAn), corrB = __expf(mB - mBn);
        mA = mAn; mB = mBn;

        float sumA = 0.f, sumB = 0.f;
        #pragma unroll
        for (int ch = 0; ch < 8; ch++) {
            sc[ch][0] = __expf(sc[ch][0] - mA);
            sc[ch][1] = __expf(sc[ch][1] - mA);
            sc[ch][2] = __expf(sc[ch][2] - mB);
            sc[ch][3] = __expf(sc[ch][3] - mB);
            sumA += sc[ch][0] + sc[ch][1];
            sumB += sc[ch][2] + sc[ch][3];
        }
        sumA += __shfl_xor_sync(0xffffffffu, sumA, 1);
        sumA += __shfl_xor_sync(0xffffffffu, sumA, 2);
        sumB += __shfl_xor_sync(0xffffffffu, sumB, 1);
        sumB += __shfl_xor_sync(0xffffffffu, sumB, 2);
        lA = lA * corrA + sumA;
        lB = lB * corrB + sumB;
        #pragma unroll
        for (int d = 0; d < 8; d++) {
            o[d][0] *= corrA; o[d][1] *= corrA;
            o[d][2] *= corrB; o[d][3] *= corrB;
        }

        #pragma unroll
        for (int kk = 0; kk < 4; kk++) {
            uint32_t ah_[4], al_[4];
            split_bf16x2(sc[2 * kk][0],     sc[2 * kk][1],     ah_[0], al_[0]);
            split_bf16x2(sc[2 * kk][2],     sc[2 * kk][3],     ah_[1], al_[1]);
            split_bf16x2(sc[2 * kk + 1][0], sc[2 * kk + 1][1], ah_[2], al_[2]);
            split_bf16x2(sc[2 * kk + 1][2], sc[2 * kk + 1][3], ah_[3], al_[3]);
            #pragma unroll
            for (int dc = 0; dc < 8; dc++) {
                int vrow = (dc * 8 + gid) * KVP;
                uint32_t bh_[2], bl_[2];
                bh_[0] = Vh[vrow + 8 * kk + tig]; bh_[1] = Vh[vrow + 8 * kk + tig + 4];
                bl_[0] = Vl[vrow + 8 * kk + tig]; bl_[1] = Vl[vrow + 8 * kk + tig + 4];
                mma_bf16(o[dc], ah_, bl_);
                mma_bf16(o[dc], al_, bh_);
                mma_bf16(o[dc], ah_, bh_);
            }
        }
        __syncthreads();
    }

    float invA = 1.f / lA, invB = 1.f / lB;
    float* obase = ob + ((size_t)(b * TSEQ + qrow0)) * DIM + h * HD;
    #pragma unroll
    for (int dc = 0; dc < 8; dc++) {
        *(float2*)&obase[(size_t)gid * DIM + dc * 8 + 2 * tig] =
            make_float2(o[dc][0] * invA, o[dc][1] * invA);
        *(float2*)&obase[(size_t)(gid + 8) * DIM + dc * 8 + 2 * tig] =
            make_float2(o[dc][2] * invB, o[dc][3] * invB);
    }
}

// ---------------- launch ----------------------------------------------------------
extern "C" void kernel_launch(void* const* d_in, const int* in_sizes, int n_in,
                              void* d_out, int out_size) {
    const float* x    = (const float*)d_in[0];
    const float* cosp = (const float*)d_in[1];
    const float* sinp = (const float*)d_in[2];
    const float* wq_w = (const float*)d_in[3];
    const float* wk_w = (const float*)d_in[4];
    const float* wv_w = (const float*)d_in[5];
    const float* wo_w = (const float*)d_in[6];
    float* out = (float*)d_out;

    void* p;
    cudaGetSymbolAddress(&p, g_wi); int8_t* wip = (int8_t*)p;
    cudaGetSymbolAddress(&p, g_ws); float*  wsp = (float*)p;
    cudaGetSymbolAddress(&p, g_xi); int8_t* xip = (int8_t*)p;
    cudaGetSymbolAddress(&p, g_sx); float*  sxp = (float*)p;
    cudaGetSymbolAddress(&p, g_q);  float*  qp  = (float*)p;
    cudaGetSymbolAddress(&p, g_k);  float*  kp  = (float*)p;
    cudaGetSymbolAddress(&p, g_v);  float*  vp  = (float*)p;
    cudaGetSymbolAddress(&p, g_ao); float*  aop = (float*)p;

    cudaFuncSetAttribute(gemm_i8mma_kernel, cudaFuncAttributeMaxDynamicSharedMemorySize, SMEM_GEMM);

    quant_w_kernel<<<4 * DIM * 8, 128>>>(wq_w, wk_w, wv_w, wo_w);
    quant_x_kernel<<<BT, 256>>>(x, xip, sxp);

    dim3 gq(DIM / 128, BT / 128, 3);
    gemm_i8mma_kernel<<<gq, 512, SMEM_GEMM>>>(xip, wip, wsp, sxp, qp, kp, vp);

    int npairs = 2 * TSEQ * NH * 32;
    rope_k_kernel<<<(npairs + 255) / 256, 256>>>(kp, cosp, sinp);

    attn_mma_kernel<<<dim3(TSEQ / 64, 2 * NH), 128>>>(qp, kp, vp, aop, cosp, sinp);

    quant_x_kernel<<<BT, 256>>>(aop, xip, sxp);
    dim3 go(DIM / 128, BT / 128, 1);
    gemm_i8mma_kernel<<<go, 512, SMEM_GEMM>>>(xip, wip + 3 * (size_t)DIM * DIM,
                                              wsp + 3 * DIM * 8, sxp, out, out, out);
}